// round 13
// baseline (speedup 1.0000x reference)
#include <cuda_runtime.h>
#include <cstddef>
#include <cstdint>

// Shapes (fixed by the problem):
// B=32, T=32, K=196, H=512, A=512
#define Bv   32
#define Tv   32
#define Kv   196
#define Hv   512
#define Av   512

// ---------------- scratch (no cudaMalloc allowed) ----------------
__device__ float g_cv[Bv * Kv * Av];   // att_feats @ Wv   (6272 x 512)
__device__ float g_cg[Bv * Tv * Av];   // hiddens   @ Wg   (1024 x 512)
__device__ float g_cs[Bv * Tv * Av];   // sentinel  @ Ws   (1024 x 512)
__device__ float g_z [Bv * Tv * Kv];   // z_t logits       (1024 x 196)

// ---------------- helpers ----------------
__device__ __forceinline__ float fast_tanh(float x) {
    float y;
    asm("tanh.approx.f32 %0, %1;" : "=f"(y) : "f"(x));
    return y;
}

__device__ __forceinline__ uint32_t f2tf32(float x) {
    uint32_t y;
    asm("cvt.rna.tf32.f32 %0, %1;" : "=r"(y) : "f"(x));
    return y;
}

__device__ __forceinline__ void mma_tf32(float c[4], const uint32_t a[4], const uint32_t b[2]) {
    asm volatile(
        "mma.sync.aligned.m16n8k8.row.col.f32.tf32.tf32.f32 "
        "{%0,%1,%2,%3}, {%4,%5,%6,%7}, {%8,%9}, {%0,%1,%2,%3};\n"
        : "+f"(c[0]), "+f"(c[1]), "+f"(c[2]), "+f"(c[3])
        : "r"(a[0]), "r"(a[1]), "r"(a[2]), "r"(a[3]), "r"(b[0]), "r"(b[1]));
}

__device__ __forceinline__ void cp16(uint32_t dst_smem, const void* src) {
    asm volatile("cp.async.ca.shared.global [%0], [%1], 16;\n"
                 :: "r"(dst_smem), "l"(src));
}
__device__ __forceinline__ void cp_commit() {
    asm volatile("cp.async.commit_group;\n");
}
template <int N>
__device__ __forceinline__ void cp_wait() {
    asm volatile("cp.async.wait_group %0;\n" :: "n"(N));
}
__device__ __forceinline__ uint32_t smem_u32(const void* p) {
    uint32_t a;
    asm("{ .reg .u64 t; cvta.to.shared.u64 t, %1; cvt.u32.u64 %0, t; }" : "=r"(a) : "l"(p));
    return a;
}

__device__ __forceinline__ float warp_sum(float v) {
#pragma unroll
    for (int o = 16; o > 0; o >>= 1) v += __shfl_xor_sync(0xffffffffu, v, o);
    return v;
}

__device__ __forceinline__ float warp_max(float v) {
#pragma unroll
    for (int o = 16; o > 0; o >>= 1) v = fmaxf(v, __shfl_xor_sync(0xffffffffu, v, o));
    return v;
}

// ---------------- fused TF32 tensor-core GEMM (3 GEMMs, one launch) ----------------
// C[Mx512] = A[Mx512] * W[512x512], row-major fp32.
// BM=128, BN=64, BK=32, 128 threads = 4 warps (2M x 2N), warp tile 64x32
// (4x4 m16n8k8 mma). cp.async 2-stage pipeline. Dynamic smem 55296 B.
// Block routing: [0,392) -> GEMM0 (M=6272), [392,456) -> GEMM1, [456,520) -> GEMM2.
#define GK 512
#define GN 512
#define A_STRIDE 36          // 32 + 4 pad, conflict-free frag reads, 16B-aligned rows
#define B_STRIDE 72          // 64 + 8 pad
#define A_FLOATS (128 * A_STRIDE)    // 4608
#define B_FLOATS (32 * B_STRIDE)     // 2304
#define STAGE_FLOATS (A_FLOATS + B_FLOATS)  // 6912 (27648 B); 2 stages = 55296 B

__global__ __launch_bounds__(128, 4) void gemm3_tf32(
    const float* __restrict__ A0, const float* __restrict__ W0, float* __restrict__ C0,
    const float* __restrict__ A1, const float* __restrict__ W1, float* __restrict__ C1,
    const float* __restrict__ A2, const float* __restrict__ W2, float* __restrict__ C2)
{
    extern __shared__ float sm[];

    const int bid = blockIdx.x;
    const float *A, *W;
    float* C;
    int mblk, nblk;
    if (bid < 392)      { A = A0; W = W0; C = C0; mblk = bid >> 3;        nblk = bid & 7; }
    else if (bid < 456) { A = A1; W = W1; C = C1; mblk = (bid - 392) >> 3; nblk = (bid - 392) & 7; }
    else                { A = A2; W = W2; C = C2; mblk = (bid - 456) >> 3; nblk = (bid - 456) & 7; }

    const int row0 = mblk * 128;
    const int col0 = nblk * 64;

    const int tid  = threadIdx.x;
    const int wid  = tid >> 5;
    const int lane = tid & 31;
    const int wm   = wid & 1;       // M warp (0..1) -> 64 rows
    const int wn   = wid >> 1;      // N warp (0..1) -> 32 cols
    const int g    = lane >> 2;     // 0..7
    const int q    = lane & 3;      // 0..3

    // global->smem load mapping
    const int aRowB = tid >> 3;           // + j*16, j=0..7
    const int aC4   = (tid & 7) * 4;
    const int bRowB = tid >> 4;           // + j*8,  j=0..3
    const int bC4   = (tid & 15) * 4;

    const uint32_t smb = smem_u32(sm);

    // stage load (cp.async)
    auto load_stage = [&](int s, int kk) {
        uint32_t as = smb + (uint32_t)(s * STAGE_FLOATS) * 4u;
        uint32_t bs = as + A_FLOATS * 4u;
#pragma unroll
        for (int j = 0; j < 8; j++) {
            int r = aRowB + j * 16;
            cp16(as + (uint32_t)(r * A_STRIDE + aC4) * 4u,
                 &A[(size_t)(row0 + r) * GK + kk + aC4]);
        }
#pragma unroll
        for (int j = 0; j < 4; j++) {
            int r = bRowB + j * 8;
            cp16(bs + (uint32_t)(r * B_STRIDE + bC4) * 4u,
                 &W[(size_t)(kk + r) * GN + col0 + bC4]);
        }
    };

    float acc[4][4][4];
#pragma unroll
    for (int mi = 0; mi < 4; mi++)
#pragma unroll
        for (int ni = 0; ni < 4; ni++)
#pragma unroll
            for (int j = 0; j < 4; j++) acc[mi][ni][j] = 0.f;

    load_stage(0, 0);
    cp_commit();

    const int NIT = GK / 32;   // 16
    for (int it = 0; it < NIT; it++) {
        if (it + 1 < NIT) {
            load_stage((it + 1) & 1, (it + 1) * 32);
            cp_commit();
            cp_wait<1>();
        } else {
            cp_wait<0>();
        }
        __syncthreads();

        const float* As = sm + (it & 1) * STAGE_FLOATS;
        const float* Bs = As + A_FLOATS;

#pragma unroll
        for (int k0 = 0; k0 < 32; k0 += 8) {
            uint32_t afrag[4][4];
            uint32_t bfrag[4][2];
#pragma unroll
            for (int mi = 0; mi < 4; mi++) {
                const float* ap = As + (wm * 64 + mi * 16 + g) * A_STRIDE + k0 + q;
                afrag[mi][0] = f2tf32(ap[0]);
                afrag[mi][1] = f2tf32(ap[8 * A_STRIDE]);
                afrag[mi][2] = f2tf32(ap[4]);
                afrag[mi][3] = f2tf32(ap[8 * A_STRIDE + 4]);
            }
#pragma unroll
            for (int ni = 0; ni < 4; ni++) {
                const float* bp = Bs + (k0 + q) * B_STRIDE + wn * 32 + ni * 8 + g;
                bfrag[ni][0] = f2tf32(bp[0]);
                bfrag[ni][1] = f2tf32(bp[4 * B_STRIDE]);
            }
#pragma unroll
            for (int mi = 0; mi < 4; mi++)
#pragma unroll
                for (int ni = 0; ni < 4; ni++)
                    mma_tf32(acc[mi][ni], afrag[mi], bfrag[ni]);
        }
        __syncthreads();
    }

    // epilogue
#pragma unroll
    for (int mi = 0; mi < 4; mi++) {
#pragma unroll
        for (int ni = 0; ni < 4; ni++) {
            int r = row0 + wm * 64 + mi * 16 + g;
            int c = col0 + wn * 32 + ni * 8 + q * 2;
            *(float2*)&C[(size_t)r * GN + c]       = make_float2(acc[mi][ni][0], acc[mi][ni][1]);
            *(float2*)&C[(size_t)(r + 8) * GN + c] = make_float2(acc[mi][ni][2], acc[mi][ni][3]);
        }
    }
}

// ---------------- z_t kernel (v3: warp-per-(k, t-half), balanced) ----------------
// z[b,t,k] = sum_a tanh(cv[b,k,a] + cg[b,t,a]) * wh[a]
// grid (49, 32) = 1568 blocks, 4 k per block. All 32 cg rows live in 64KB
// dynamic smem (loaded once). Each of the 8 warps owns exactly one
// (k, 16-row t-half) task: cv row in 16 regs (read once from L2), 16 fp32
// accumulators, 256 MUFU warp-instrs, no cross-warp sync after the load.
__global__ __launch_bounds__(256) void zt_kernel(
    const float* __restrict__ cv, const float* __restrict__ cg,
    const float* __restrict__ wh, float* __restrict__ z)
{
    extern __shared__ float cg_sh[];   // 32 * 512 floats = 64 KB
    const int b = blockIdx.y;
    const int kbase = blockIdx.x * 4;  // 0..192
    const int tid = threadIdx.x;
    const int w = tid >> 5, lane = tid & 31;

    // stage whole cg[b] (32 x 512) into smem via cp.async
    const uint32_t cgs = smem_u32(cg_sh);
    const float* src = cg + (size_t)b * Tv * Av;
#pragma unroll
    for (int i = tid; i < (Tv * Av) / 4; i += 256)
        cp16(cgs + (uint32_t)i * 16u, src + (size_t)i * 4);
    cp_commit();

    float whr[16];
#pragma unroll
    for (int i = 0; i < 16; i++) whr[i] = __ldg(wh + i * 32 + lane);

    const int k  = kbase + (w & 3);    // warp's k
    const int th = w >> 2;             // warp's t-half (0/1)

    // cv row in registers (read once)
    const float* cvrow = cv + ((size_t)b * Kv + k) * Av + lane;
    float cvr[16];
#pragma unroll
    for (int i = 0; i < 16; i++) cvr[i] = cvrow[i * 32];

    cp_wait<0>();
    __syncthreads();

    float s[16];
#pragma unroll
    for (int t = 0; t < 16; t++) s[t] = 0.f;

    const float* cgb = cg_sh + (th * 16) * Av + lane;
#pragma unroll
    for (int i = 0; i < 16; i++) {
        const float cvv = cvr[i];
        const float whv = whr[i];
        const float* cgc = cgb + i * 32;
#pragma unroll
        for (int t = 0; t < 16; t++)
            s[t] = fmaf(fast_tanh(cvv + cgc[t * Av]), whv, s[t]);
    }

    // 16 independent 5-deep shfl chains -> overlap
#pragma unroll
    for (int t = 0; t < 16; t++) s[t] = warp_sum(s[t]);

    if (lane == 0) {
#pragma unroll
        for (int t = 0; t < 16; t++)
            z[((size_t)b * Tv + th * 16 + t) * Kv + k] = s[t];
    }
}

// ---------------- softmax + sentinel gate ----------------
__global__ __launch_bounds__(256) void softmax_kernel(
    const float* __restrict__ z, const float* __restrict__ csraw,
    const float* __restrict__ cg, const float* __restrict__ wh,
    float* __restrict__ alpha_out, float* __restrict__ beta_out)
{
    const int row = blockIdx.x;       // b*T + t
    const int tid = threadIdx.x;
    const int w = tid >> 5, lane = tid & 31;
    __shared__ float sred[8];
    __shared__ float sred2[8];

    // z_ext partial
    const float* cs_r = csraw + (size_t)row * Av;
    const float* cg_r = cg + (size_t)row * Av;
    float p = 0.f;
#pragma unroll
    for (int it = 0; it < 2; it++) {
        int a = tid + it * 256;
        p = fmaf(fast_tanh(cs_r[a] + cg_r[a]), __ldg(wh + a), p);
    }
    p = warp_sum(p);
    if (lane == 0) sred[w] = p;

    float v = (tid < Kv) ? z[(size_t)row * Kv + tid] : -1e30f;
    float m = warp_max(v);
    if (lane == 0) sred2[w] = m;
    __syncthreads();

    float zext = 0.f, m1 = -1e30f;
#pragma unroll
    for (int i = 0; i < 8; i++) { zext += sred[i]; m1 = fmaxf(m1, sred2[i]); }
    __syncthreads();

    float e = (tid < Kv) ? __expf(v - m1) : 0.f;
    float s = warp_sum(e);
    if (lane == 0) sred[w] = s;
    __syncthreads();

    float s1 = 0.f;
#pragma unroll
    for (int i = 0; i < 8; i++) s1 += sred[i];

    if (tid < Kv) alpha_out[(size_t)row * Kv + tid] = e / s1;

    if (tid == 0) {
        float m2 = fmaxf(m1, zext);
        float s2 = s1 * __expf(m1 - m2) + __expf(zext - m2);
        beta_out[row] = __expf(zext - m2) / s2;
    }
}

// ---------------- c_t + blend (v5: 3-stage cp.async ring) ----------------
// c_t[b,t,h] = sum_k alpha[b,t,k]*att[b,k,h];  chat = beta*sent + (1-beta)*c_t
// grid (8 h-tiles of 64, 32 b), 256 threads = 64 h-lanes x 4 t-groups (8 t each).
// att streamed through a 3-stage cp.async ring in 28-row chunks -> 2 chunks
// in flight while computing a third; one barrier per chunk.
#define CT_CHUNK 28                      // 196 = 7 * 28, divisible by 4
#define CT_CHUNK_FLOATS (CT_CHUNK * 64)  // 1792 floats = 7168 B

__global__ __launch_bounds__(256) void ct_kernel(
    const float* __restrict__ att, const float* __restrict__ alpha,
    const float* __restrict__ beta, const float* __restrict__ sent,
    float* __restrict__ chat)
{
    __shared__ float al[Tv * Kv];                 // 25088 B
    __shared__ float att_sh[3][CT_CHUNK_FLOATS];  // 21504 B
    __shared__ float be[Tv];
    const int b  = blockIdx.y;
    const int h0 = blockIdx.x * 64;
    const int tid = threadIdx.x;
    const int hl = tid & 63;       // h lane 0..63
    const int t0 = (tid >> 6) * 8; // t group base: 0,8,16,24

    const uint32_t att_sm[3] = { smem_u32(att_sh[0]), smem_u32(att_sh[1]), smem_u32(att_sh[2]) };
    const float* attg = att + (size_t)b * Kv * Hv + h0;

    auto load_chunk = [&](int s, int c) {
        const float* src0 = attg + (size_t)c * CT_CHUNK * Hv;
#pragma unroll
        for (int i = tid; i < 448; i += 256) {
            int r = i >> 4;              // 0..27
            int c4 = (i & 15) * 4;       // 0..60
            cp16(att_sm[s] + (uint32_t)(r * 64 + c4) * 4u,
                 src0 + (size_t)r * Hv + c4);
        }
    };

    // alpha + beta staging (plain loads, small)
    for (int i = tid; i < Tv * Kv; i += 256) al[i] = alpha[(size_t)b * Tv * Kv + i];
    if (tid < Tv) be[tid] = beta[b * Tv + tid];

    load_chunk(0, 0); cp_commit();
    load_chunk(1, 1); cp_commit();

    float acc[8];
#pragma unroll
    for (int t = 0; t < 8; t++) acc[t] = 0.f;

    for (int c = 0; c < 7; c++) {
        // wait for chunk c (allow chunk c+1 to stay in flight)
        if (c == 6) cp_wait<0>(); else cp_wait<1>();
        // (a) makes other threads' cp.async data for chunk c visible
        // (b) ensures all warps finished reading buffer (c-1)%3 before the
        //     load of chunk c+2 below overwrites it
        __syncthreads();
        if (c + 2 < 7) { load_chunk((c + 2) % 3, c + 2); cp_commit(); }

        const float* ash = att_sh[c % 3];
        const int kbase = c * CT_CHUNK;
#pragma unroll
        for (int kk = 0; kk < CT_CHUNK; kk += 4) {
            float a0 = ash[(kk + 0) * 64 + hl];
            float a1 = ash[(kk + 1) * 64 + hl];
            float a2 = ash[(kk + 2) * 64 + hl];
            float a3 = ash[(kk + 3) * 64 + hl];
#pragma unroll
            for (int t = 0; t < 8; t++) {
                float4 v = *(const float4*)&al[(t0 + t) * Kv + kbase + kk];
                acc[t] = fmaf(v.x, a0, acc[t]);
                acc[t] = fmaf(v.y, a1, acc[t]);
                acc[t] = fmaf(v.z, a2, acc[t]);
                acc[t] = fmaf(v.w, a3, acc[t]);
            }
        }
    }

#pragma unroll
    for (int t = 0; t < 8; t++) {
        float bt = be[t0 + t];
        size_t idx = ((size_t)b * Tv + t0 + t) * Hv + h0 + hl;
        chat[idx] = bt * sent[idx] + (1.f - bt) * acc[t];
    }
}

// ---------------- launch ----------------
extern "C" void kernel_launch(void* const* d_in, const int* in_sizes, int n_in,
                              void* d_out, int out_size)
{
    const float* att = (const float*)d_in[0];   // (B,K,H)
    const float* hid = (const float*)d_in[1];   // (B,T,H)
    const float* sen = (const float*)d_in[2];   // (B,T,H)
    const float* Wv  = (const float*)d_in[3];   // (H,A)
    const float* Wg  = (const float*)d_in[4];
    const float* Ws  = (const float*)d_in[5];
    const float* wh  = (const float*)d_in[6];   // (A,)

    float* out   = (float*)d_out;
    float* chat  = out;                                  // B*T*H
    float* alpha = out + (size_t)Bv * Tv * Hv;           // B*T*K
    float* beta  = alpha + (size_t)Bv * Tv * Kv;         // B*T

    float *cv, *cg, *cs, *zb;
    cudaGetSymbolAddress((void**)&cv, g_cv);
    cudaGetSymbolAddress((void**)&cg, g_cg);
    cudaGetSymbolAddress((void**)&cs, g_cs);
    cudaGetSymbolAddress((void**)&zb, g_z);

    static_assert(STAGE_FLOATS * 2 * 4 == 55296, "smem size");
    cudaFuncSetAttribute(gemm3_tf32, cudaFuncAttributeMaxDynamicSharedMemorySize, 55296);
    cudaFuncSetAttribute(zt_kernel, cudaFuncAttributeMaxDynamicSharedMemorySize, Tv * Av * 4);

    // one fused launch: cv (392 blocks) + cg (64) + cs (64)
    gemm3_tf32<<<520, 128, 55296>>>(att, Wv, cv, hid, Wg, cg, sen, Ws, cs);

    dim3 gz(49, Bv);   // 1568 blocks, 4 k each, warp-per-(k, t-half)
    zt_kernel<<<gz, 256, Tv * Av * 4>>>(cv, cg, wh, zb);

    softmax_kernel<<<Bv * Tv, 256>>>(zb, cs, cg, wh, alpha, beta);

    dim3 gc(Hv / 64, Bv);   // 8 x 32 = 256 blocks
    ct_kernel<<<gc, 256>>>(att, alpha, beta, sen, chat);
}

// round 15
// speedup vs baseline: 1.5425x; 1.5425x over previous
#include <cuda_runtime.h>
#include <cstddef>
#include <cstdint>

// Shapes (fixed by the problem):
// B=32, T=32, K=196, H=512, A=512
#define Bv   32
#define Tv   32
#define Kv   196
#define Hv   512
#define Av   512

// ---------------- scratch (no cudaMalloc allowed) ----------------
__device__ float g_cv[Bv * Kv * Av];   // att_feats @ Wv   (6272 x 512)
__device__ float g_cg[Bv * Tv * Av];   // hiddens   @ Wg   (1024 x 512)
__device__ float g_cs[Bv * Tv * Av];   // sentinel  @ Ws   (1024 x 512)
__device__ float g_z [Bv * Tv * Kv];   // z_t logits       (1024 x 196)

// ---------------- helpers ----------------
__device__ __forceinline__ float fast_tanh(float x) {
    float y;
    asm("tanh.approx.f32 %0, %1;" : "=f"(y) : "f"(x));
    return y;
}

__device__ __forceinline__ uint32_t f2tf32(float x) {
    uint32_t y;
    asm("cvt.rna.tf32.f32 %0, %1;" : "=r"(y) : "f"(x));
    return y;
}

__device__ __forceinline__ void mma_tf32(float c[4], const uint32_t a[4], const uint32_t b[2]) {
    asm volatile(
        "mma.sync.aligned.m16n8k8.row.col.f32.tf32.tf32.f32 "
        "{%0,%1,%2,%3}, {%4,%5,%6,%7}, {%8,%9}, {%0,%1,%2,%3};\n"
        : "+f"(c[0]), "+f"(c[1]), "+f"(c[2]), "+f"(c[3])
        : "r"(a[0]), "r"(a[1]), "r"(a[2]), "r"(a[3]), "r"(b[0]), "r"(b[1]));
}

__device__ __forceinline__ void cp16(uint32_t dst_smem, const void* src) {
    asm volatile("cp.async.ca.shared.global [%0], [%1], 16;\n"
                 :: "r"(dst_smem), "l"(src));
}
__device__ __forceinline__ void cp_commit() {
    asm volatile("cp.async.commit_group;\n");
}
template <int N>
__device__ __forceinline__ void cp_wait() {
    asm volatile("cp.async.wait_group %0;\n" :: "n"(N));
}
__device__ __forceinline__ uint32_t smem_u32(const void* p) {
    uint32_t a;
    asm("{ .reg .u64 t; cvta.to.shared.u64 t, %1; cvt.u32.u64 %0, t; }" : "=r"(a) : "l"(p));
    return a;
}

__device__ __forceinline__ float warp_sum(float v) {
#pragma unroll
    for (int o = 16; o > 0; o >>= 1) v += __shfl_xor_sync(0xffffffffu, v, o);
    return v;
}

__device__ __forceinline__ float warp_max(float v) {
#pragma unroll
    for (int o = 16; o > 0; o >>= 1) v = fmaxf(v, __shfl_xor_sync(0xffffffffu, v, o));
    return v;
}

// ---------------- fused TF32 tensor-core GEMM (3 GEMMs, one launch) ----------------
// C[Mx512] = A[Mx512] * W[512x512], row-major fp32.
// BM=128, BN=64, BK=32, 128 threads = 4 warps (2M x 2N), warp tile 64x32
// (4x4 m16n8k8 mma). cp.async 2-stage pipeline. Dynamic smem 55296 B.
// Block routing: [0,392) -> GEMM0 (M=6272), [392,456) -> GEMM1, [456,520) -> GEMM2.
#define GK 512
#define GN 512
#define A_STRIDE 36          // 32 + 4 pad, conflict-free frag reads, 16B-aligned rows
#define B_STRIDE 72          // 64 + 8 pad
#define A_FLOATS (128 * A_STRIDE)    // 4608
#define B_FLOATS (32 * B_STRIDE)     // 2304
#define STAGE_FLOATS (A_FLOATS + B_FLOATS)  // 6912 (27648 B); 2 stages = 55296 B

__global__ __launch_bounds__(128, 4) void gemm3_tf32(
    const float* __restrict__ A0, const float* __restrict__ W0, float* __restrict__ C0,
    const float* __restrict__ A1, const float* __restrict__ W1, float* __restrict__ C1,
    const float* __restrict__ A2, const float* __restrict__ W2, float* __restrict__ C2)
{
    extern __shared__ float sm[];

    const int bid = blockIdx.x;
    const float *A, *W;
    float* C;
    int mblk, nblk;
    if (bid < 392)      { A = A0; W = W0; C = C0; mblk = bid >> 3;        nblk = bid & 7; }
    else if (bid < 456) { A = A1; W = W1; C = C1; mblk = (bid - 392) >> 3; nblk = (bid - 392) & 7; }
    else                { A = A2; W = W2; C = C2; mblk = (bid - 456) >> 3; nblk = (bid - 456) & 7; }

    const int row0 = mblk * 128;
    const int col0 = nblk * 64;

    const int tid  = threadIdx.x;
    const int wid  = tid >> 5;
    const int lane = tid & 31;
    const int wm   = wid & 1;       // M warp (0..1) -> 64 rows
    const int wn   = wid >> 1;      // N warp (0..1) -> 32 cols
    const int g    = lane >> 2;     // 0..7
    const int q    = lane & 3;      // 0..3

    // global->smem load mapping
    const int aRowB = tid >> 3;           // + j*16, j=0..7
    const int aC4   = (tid & 7) * 4;
    const int bRowB = tid >> 4;           // + j*8,  j=0..3
    const int bC4   = (tid & 15) * 4;

    const uint32_t smb = smem_u32(sm);

    // stage load (cp.async)
    auto load_stage = [&](int s, int kk) {
        uint32_t as = smb + (uint32_t)(s * STAGE_FLOATS) * 4u;
        uint32_t bs = as + A_FLOATS * 4u;
#pragma unroll
        for (int j = 0; j < 8; j++) {
            int r = aRowB + j * 16;
            cp16(as + (uint32_t)(r * A_STRIDE + aC4) * 4u,
                 &A[(size_t)(row0 + r) * GK + kk + aC4]);
        }
#pragma unroll
        for (int j = 0; j < 4; j++) {
            int r = bRowB + j * 8;
            cp16(bs + (uint32_t)(r * B_STRIDE + bC4) * 4u,
                 &W[(size_t)(kk + r) * GN + col0 + bC4]);
        }
    };

    float acc[4][4][4];
#pragma unroll
    for (int mi = 0; mi < 4; mi++)
#pragma unroll
        for (int ni = 0; ni < 4; ni++)
#pragma unroll
            for (int j = 0; j < 4; j++) acc[mi][ni][j] = 0.f;

    load_stage(0, 0);
    cp_commit();

    const int NIT = GK / 32;   // 16
    for (int it = 0; it < NIT; it++) {
        if (it + 1 < NIT) {
            load_stage((it + 1) & 1, (it + 1) * 32);
            cp_commit();
            cp_wait<1>();
        } else {
            cp_wait<0>();
        }
        __syncthreads();

        const float* As = sm + (it & 1) * STAGE_FLOATS;
        const float* Bs = As + A_FLOATS;

#pragma unroll
        for (int k0 = 0; k0 < 32; k0 += 8) {
            uint32_t afrag[4][4];
            uint32_t bfrag[4][2];
#pragma unroll
            for (int mi = 0; mi < 4; mi++) {
                const float* ap = As + (wm * 64 + mi * 16 + g) * A_STRIDE + k0 + q;
                afrag[mi][0] = f2tf32(ap[0]);
                afrag[mi][1] = f2tf32(ap[8 * A_STRIDE]);
                afrag[mi][2] = f2tf32(ap[4]);
                afrag[mi][3] = f2tf32(ap[8 * A_STRIDE + 4]);
            }
#pragma unroll
            for (int ni = 0; ni < 4; ni++) {
                const float* bp = Bs + (k0 + q) * B_STRIDE + wn * 32 + ni * 8 + g;
                bfrag[ni][0] = f2tf32(bp[0]);
                bfrag[ni][1] = f2tf32(bp[4 * B_STRIDE]);
            }
#pragma unroll
            for (int mi = 0; mi < 4; mi++)
#pragma unroll
                for (int ni = 0; ni < 4; ni++)
                    mma_tf32(acc[mi][ni], afrag[mi], bfrag[ni]);
        }
        __syncthreads();
    }

    // epilogue
#pragma unroll
    for (int mi = 0; mi < 4; mi++) {
#pragma unroll
        for (int ni = 0; ni < 4; ni++) {
            int r = row0 + wm * 64 + mi * 16 + g;
            int c = col0 + wn * 32 + ni * 8 + q * 2;
            *(float2*)&C[(size_t)r * GN + c]       = make_float2(acc[mi][ni][0], acc[mi][ni][1]);
            *(float2*)&C[(size_t)(r + 8) * GN + c] = make_float2(acc[mi][ni][2], acc[mi][ni][3]);
        }
    }
}

// ---------------- z_t kernel (v2b: 7-k tiles -> 896 blocks for occupancy) ----------------
// z[b,t,k] = sum_a tanh(cv[b,k,a] + cg[b,t,a]) * wh[a]
// grid (28 k-tiles, 32 b), 256 threads. cv row in registers, cg in shared
// (two 16-row passes). 7 k's per block over 8 warps (warp 7 idle in compute)
// -> 896 blocks = ~6 blocks/SM so the MUFU pipe stays fed (v2 was capped at
// 3.03 blocks/SM by grid size = the measured 1.41x gap to the MUFU floor).
__global__ __launch_bounds__(256) void zt_kernel(
    const float* __restrict__ cv, const float* __restrict__ cg,
    const float* __restrict__ wh, float* __restrict__ z)
{
    __shared__ float cg_sh[16 * Av];
    const int b = blockIdx.y;
    const int ktile = blockIdx.x;      // 0..27, 7 k's each
    const int tid = threadIdx.x;
    const int w = tid >> 5, lane = tid & 31;

    float whr[16];
#pragma unroll
    for (int i = 0; i < 16; i++) whr[i] = __ldg(wh + i * 32 + lane);

    for (int th = 0; th < 2; th++) {
        __syncthreads();
        const float4* src = (const float4*)(cg + ((size_t)b * Tv + th * 16) * Av);
        float4* dst = (float4*)cg_sh;
        for (int i = tid; i < 16 * Av / 4; i += 256) dst[i] = src[i];
        __syncthreads();

        for (int kl = w; kl < 7; kl += 8) {
            const int k = ktile * 7 + kl;
            const float* cvrow = cv + ((size_t)b * Kv + k) * Av + lane;
            float cvr[16];
#pragma unroll
            for (int i = 0; i < 16; i++) cvr[i] = cvrow[i * 32];

            float s[16];
#pragma unroll
            for (int t = 0; t < 16; t++) s[t] = 0.f;

#pragma unroll
            for (int i = 0; i < 16; i++) {
                const float cvv = cvr[i];
                const float whv = whr[i];
                const float* cgc = cg_sh + i * 32 + lane;
#pragma unroll
                for (int t = 0; t < 16; t++)
                    s[t] = fmaf(fast_tanh(cvv + cgc[t * Av]), whv, s[t]);
            }

            // 16 independent 5-deep shfl chains -> overlap
#pragma unroll
            for (int t = 0; t < 16; t++) s[t] = warp_sum(s[t]);

            if (lane == 0) {
#pragma unroll
                for (int t = 0; t < 16; t++)
                    z[((size_t)b * Tv + th * 16 + t) * Kv + k] = s[t];
            }
        }
    }
}

// ---------------- softmax + sentinel gate ----------------
__global__ __launch_bounds__(256) void softmax_kernel(
    const float* __restrict__ z, const float* __restrict__ csraw,
    const float* __restrict__ cg, const float* __restrict__ wh,
    float* __restrict__ alpha_out, float* __restrict__ beta_out)
{
    const int row = blockIdx.x;       // b*T + t
    const int tid = threadIdx.x;
    const int w = tid >> 5, lane = tid & 31;
    __shared__ float sred[8];
    __shared__ float sred2[8];

    // z_ext partial
    const float* cs_r = csraw + (size_t)row * Av;
    const float* cg_r = cg + (size_t)row * Av;
    float p = 0.f;
#pragma unroll
    for (int it = 0; it < 2; it++) {
        int a = tid + it * 256;
        p = fmaf(fast_tanh(cs_r[a] + cg_r[a]), __ldg(wh + a), p);
    }
    p = warp_sum(p);
    if (lane == 0) sred[w] = p;

    float v = (tid < Kv) ? z[(size_t)row * Kv + tid] : -1e30f;
    float m = warp_max(v);
    if (lane == 0) sred2[w] = m;
    __syncthreads();

    float zext = 0.f, m1 = -1e30f;
#pragma unroll
    for (int i = 0; i < 8; i++) { zext += sred[i]; m1 = fmaxf(m1, sred2[i]); }
    __syncthreads();

    float e = (tid < Kv) ? __expf(v - m1) : 0.f;
    float s = warp_sum(e);
    if (lane == 0) sred[w] = s;
    __syncthreads();

    float s1 = 0.f;
#pragma unroll
    for (int i = 0; i < 8; i++) s1 += sred[i];

    if (tid < Kv) alpha_out[(size_t)row * Kv + tid] = e / s1;

    if (tid == 0) {
        float m2 = fmaxf(m1, zext);
        float s2 = s1 * __expf(m1 - m2) + __expf(zext - m2);
        beta_out[row] = __expf(zext - m2) / s2;
    }
}

// ---------------- c_t + blend (v4: cp.async-pipelined att stream) ----------------
// c_t[b,t,h] = sum_k alpha[b,t,k]*att[b,k,h];  chat = beta*sent + (1-beta)*c_t
// grid (8 h-tiles of 64, 32 b), 256 threads = 64 h-lanes x 4 t-groups (8 t each).
// att streamed through a 2-stage cp.async smem pipeline in 28-row chunks
// (MLP comes from LDGSTS depth, not registers). alpha in smem as float4.
#define CT_CHUNK 28                      // 196 = 7 * 28, divisible by 4
#define CT_CHUNK_FLOATS (CT_CHUNK * 64)  // 1792 floats = 7168 B

__global__ __launch_bounds__(256) void ct_kernel(
    const float* __restrict__ att, const float* __restrict__ alpha,
    const float* __restrict__ beta, const float* __restrict__ sent,
    float* __restrict__ chat)
{
    __shared__ float al[Tv * Kv];                 // 25088 B
    __shared__ float att_sh[2][CT_CHUNK_FLOATS];  // 14336 B
    __shared__ float be[Tv];
    const int b  = blockIdx.y;
    const int h0 = blockIdx.x * 64;
    const int tid = threadIdx.x;
    const int hl = tid & 63;       // h lane 0..63
    const int t0 = (tid >> 6) * 8; // t group base: 0,8,16,24

    const uint32_t att_sm[2] = { smem_u32(att_sh[0]), smem_u32(att_sh[1]) };
    const float* attg = att + (size_t)b * Kv * Hv + h0;

    auto load_chunk = [&](int s, int c) {
        const float* src0 = attg + (size_t)c * CT_CHUNK * Hv;
#pragma unroll
        for (int i = tid; i < 448; i += 256) {
            int r = i >> 4;              // 0..27
            int c4 = (i & 15) * 4;       // 0..60
            cp16(att_sm[s] + (uint32_t)(r * 64 + c4) * 4u,
                 src0 + (size_t)r * Hv + c4);
        }
    };

    // alpha + beta staging (plain loads, small)
    for (int i = tid; i < Tv * Kv; i += 256) al[i] = alpha[(size_t)b * Tv * Kv + i];
    if (tid < Tv) be[tid] = beta[b * Tv + tid];

    load_chunk(0, 0);
    cp_commit();

    float acc[8];
#pragma unroll
    for (int t = 0; t < 8; t++) acc[t] = 0.f;

    for (int c = 0; c < 7; c++) {
        if (c + 1 < 7) {
            load_chunk((c + 1) & 1, c + 1);
            cp_commit();
            cp_wait<1>();
        } else {
            cp_wait<0>();
        }
        __syncthreads();

        const float* ash = att_sh[c & 1];
        const int kbase = c * CT_CHUNK;
#pragma unroll
        for (int kk = 0; kk < CT_CHUNK; kk += 4) {
            float a0 = ash[(kk + 0) * 64 + hl];
            float a1 = ash[(kk + 1) * 64 + hl];
            float a2 = ash[(kk + 2) * 64 + hl];
            float a3 = ash[(kk + 3) * 64 + hl];
#pragma unroll
            for (int t = 0; t < 8; t++) {
                float4 v = *(const float4*)&al[(t0 + t) * Kv + kbase + kk];
                acc[t] = fmaf(v.x, a0, acc[t]);
                acc[t] = fmaf(v.y, a1, acc[t]);
                acc[t] = fmaf(v.z, a2, acc[t]);
                acc[t] = fmaf(v.w, a3, acc[t]);
            }
        }
        __syncthreads();
    }

#pragma unroll
    for (int t = 0; t < 8; t++) {
        float bt = be[t0 + t];
        size_t idx = ((size_t)b * Tv + t0 + t) * Hv + h0 + hl;
        chat[idx] = bt * sent[idx] + (1.f - bt) * acc[t];
    }
}

// ---------------- launch ----------------
extern "C" void kernel_launch(void* const* d_in, const int* in_sizes, int n_in,
                              void* d_out, int out_size)
{
    const float* att = (const float*)d_in[0];   // (B,K,H)
    const float* hid = (const float*)d_in[1];   // (B,T,H)
    const float* sen = (const float*)d_in[2];   // (B,T,H)
    const float* Wv  = (const float*)d_in[3];   // (H,A)
    const float* Wg  = (const float*)d_in[4];
    const float* Ws  = (const float*)d_in[5];
    const float* wh  = (const float*)d_in[6];   // (A,)

    float* out   = (float*)d_out;
    float* chat  = out;                                  // B*T*H
    float* alpha = out + (size_t)Bv * Tv * Hv;           // B*T*K
    float* beta  = alpha + (size_t)Bv * Tv * Kv;         // B*T

    float *cv, *cg, *cs, *zb;
    cudaGetSymbolAddress((void**)&cv, g_cv);
    cudaGetSymbolAddress((void**)&cg, g_cg);
    cudaGetSymbolAddress((void**)&cs, g_cs);
    cudaGetSymbolAddress((void**)&zb, g_z);

    static_assert(STAGE_FLOATS * 2 * 4 == 55296, "smem size");
    cudaFuncSetAttribute(gemm3_tf32, cudaFuncAttributeMaxDynamicSharedMemorySize, 55296);

    // one fused launch: cv (392 blocks) + cg (64) + cs (64)
    gemm3_tf32<<<520, 128, 55296>>>(att, Wv, cv, hid, Wg, cg, sen, Ws, cs);

    dim3 gz(28, Bv);   // 896 blocks, 7 k each
    zt_kernel<<<gz, 256>>>(cv, cg, wh, zb);

    softmax_kernel<<<Bv * Tv, 256>>>(zb, cs, cg, wh, alpha, beta);

    dim3 gc(Hv / 64, Bv);   // 8 x 32 = 256 blocks
    ct_kernel<<<gc, 256>>>(att, alpha, beta, sen, chat);
}